// round 10
// baseline (speedup 1.0000x reference)
#include <cuda_runtime.h>
#include <cstdint>

#define SEQ    4096
#define DIM    1024
#define HEADS  16
#define DHEAD  64
#define QBETA  0.125f   // 1/sqrt(64)

// Scratch (allocation-free rule: __device__ globals).
// All tensors below hold tf32 BIT PATTERNS — cvt.rna is hoisted to prep
// kernels; values entering every mma are bit-identical to prior rounds.
__device__ unsigned g_q[SEQ * DIM];
__device__ unsigned g_k[SEQ * DIM];
__device__ unsigned g_v[SEQ * DIM];
__device__ unsigned g_att[SEQ * DIM];
__device__ unsigned g_x[SEQ * DIM];
__device__ unsigned g_wq[DIM * DIM];
__device__ unsigned g_wk[DIM * DIM];
__device__ unsigned g_wv[DIM * DIM];
__device__ unsigned g_wo[DIM * DIM];

// ---------------------------------------------------------------------------
// tf32 helpers
// ---------------------------------------------------------------------------
__device__ __forceinline__ unsigned f2tf(float x) {
    unsigned u;
    asm("cvt.rna.tf32.f32 %0, %1;" : "=r"(u) : "f"(x));
    return u;
}

__device__ __forceinline__ void mma_tf32(float* c,
                                         unsigned a0, unsigned a1, unsigned a2, unsigned a3,
                                         unsigned b0, unsigned b1) {
    asm volatile(
        "mma.sync.aligned.m16n8k8.row.col.f32.tf32.tf32.f32 "
        "{%0,%1,%2,%3},{%4,%5,%6,%7},{%8,%9},{%0,%1,%2,%3};"
        : "+f"(c[0]), "+f"(c[1]), "+f"(c[2]), "+f"(c[3])
        : "r"(a0), "r"(a1), "r"(a2), "r"(a3), "r"(b0), "r"(b1));
}

__device__ __forceinline__ unsigned smem_u32(const void* p) {
    return (unsigned)__cvta_generic_to_shared(p);
}
__device__ __forceinline__ void cp16(unsigned dst, const void* src) {
    asm volatile("cp.async.cg.shared.global [%0], [%1], 16;" :: "r"(dst), "l"(src));
}

// ---------------------------------------------------------------------------
// prep: fp32 -> tf32 bits (grid-stride-free; n multiple of 1024)
// ---------------------------------------------------------------------------
__global__ void __launch_bounds__(256) cvt_kernel(
    const float* __restrict__ src, unsigned* __restrict__ dst)
{
    const int i = (blockIdx.x * 256 + threadIdx.x) * 4;
    float4 v = *(const float4*)&src[i];
    uint4 o = { f2tf(v.x), f2tf(v.y), f2tf(v.z), f2tf(v.w) };
    *(uint4*)&dst[i] = o;
}

// ---------------------------------------------------------------------------
// Async tf32 GEMM: block tile 128x64, K-step 32, 2-stage cp.async ping-pong.
// 256 threads = 8 warps (4x2), warp tile 32x32.
// A ld=36, B ld=72 — conflict-free fragment gathers (proven R3).
// All operands are tf32 bits -> staging is pure cp.async 16B copies.
// ---------------------------------------------------------------------------
#define GA_LD 36
#define GB_LD 72
#define G_STAGE (128 * GA_LD + 32 * GB_LD)     // 6912 uints
#define G_SMEM_BYTES (2 * G_STAGE * 4)         // 55296 B

__device__ __forceinline__ void gemm_stage(
    unsigned* buf, const unsigned* __restrict__ A, const unsigned* __restrict__ B,
    int row0, int col0, int k0, int tid)
{
    unsigned* As = buf;
    unsigned* Bs = buf + 128 * GA_LD;
#pragma unroll
    for (int p = 0; p < 4; p++) {                 // A: 128x32
        const int idx = tid + p * 256;
        const int r = idx >> 3;
        const int c = (idx & 7) * 4;
        cp16(smem_u32(&As[r * GA_LD + c]), &A[(size_t)(row0 + r) * DIM + k0 + c]);
    }
#pragma unroll
    for (int p = 0; p < 2; p++) {                 // B: 32x64
        const int idx = tid + p * 256;
        const int r = idx >> 4;
        const int c = (idx & 15) * 4;
        cp16(smem_u32(&Bs[r * GB_LD + c]), &B[(size_t)(k0 + r) * DIM + col0 + c]);
    }
    asm volatile("cp.async.commit_group;");
}

template<bool OUT_TF32>
__device__ __forceinline__ void gemm_tile_async(
    const unsigned* __restrict__ A, const unsigned* __restrict__ B,
    void* __restrict__ Cp, float alpha, const float* __restrict__ bias)
{
    extern __shared__ unsigned gsm[];

    const int tid  = threadIdx.x;
    const int lane = tid & 31;
    const int warp = tid >> 5;
    const int g = lane >> 2;
    const int t = lane & 3;
    const int wm = warp & 3;
    const int wn = warp >> 2;
    const int row0 = blockIdx.y * 128;
    const int col0 = blockIdx.x * 64;

    float acc[2][4][4];
#pragma unroll
    for (int mi = 0; mi < 2; mi++)
#pragma unroll
        for (int ni = 0; ni < 4; ni++)
#pragma unroll
            for (int e = 0; e < 4; e++) acc[mi][ni][e] = 0.f;

    gemm_stage(gsm, A, B, row0, col0, 0, tid);

    for (int ks = 0; ks < DIM / 32; ks++) {
        const int cur = ks & 1;
        unsigned* As = gsm + cur * G_STAGE;
        unsigned* Bs = As + 128 * GA_LD;

        if (ks < DIM / 32 - 1) {
            gemm_stage(gsm + (cur ^ 1) * G_STAGE, A, B, row0, col0, (ks + 1) * 32, tid);
            asm volatile("cp.async.wait_group 1;");
        } else {
            asm volatile("cp.async.wait_group 0;");
        }
        __syncthreads();

#pragma unroll
        for (int kk = 0; kk < 4; kk++) {
            unsigned a[2][4];
#pragma unroll
            for (int mi = 0; mi < 2; mi++) {
                const int rbm = wm * 32 + mi * 16;
                a[mi][0] = As[(rbm + g)     * GA_LD + kk * 8 + t];
                a[mi][1] = As[(rbm + g + 8) * GA_LD + kk * 8 + t];
                a[mi][2] = As[(rbm + g)     * GA_LD + kk * 8 + t + 4];
                a[mi][3] = As[(rbm + g + 8) * GA_LD + kk * 8 + t + 4];
            }
#pragma unroll
            for (int ni = 0; ni < 4; ni++) {
                const unsigned b0 = Bs[(kk * 8 + t)     * GB_LD + wn * 32 + ni * 8 + g];
                const unsigned b1 = Bs[(kk * 8 + t + 4) * GB_LD + wn * 32 + ni * 8 + g];
                mma_tf32(acc[0][ni], a[0][0], a[0][1], a[0][2], a[0][3], b0, b1);
                mma_tf32(acc[1][ni], a[1][0], a[1][1], a[1][2], a[1][3], b0, b1);
            }
        }
        __syncthreads();
    }

#pragma unroll
    for (int mi = 0; mi < 2; mi++) {
        const int rb = row0 + wm * 32 + mi * 16;
#pragma unroll
        for (int ni = 0; ni < 4; ni++) {
            const int cb = col0 + wn * 32 + ni * 8 + 2 * t;
            float bv0 = 0.f, bv1 = 0.f;
            if (bias) { bv0 = bias[cb]; bv1 = bias[cb + 1]; }
            float v00 = acc[mi][ni][0] * alpha + bv0;
            float v01 = acc[mi][ni][1] * alpha + bv1;
            float v10 = acc[mi][ni][2] * alpha + bv0;
            float v11 = acc[mi][ni][3] * alpha + bv1;
            if (OUT_TF32) {
                unsigned* C32 = (unsigned*)Cp;
                uint2 o0 = { f2tf(v00), f2tf(v01) };
                uint2 o1 = { f2tf(v10), f2tf(v11) };
                *(uint2*)&C32[(size_t)(rb + g)     * DIM + cb] = o0;
                *(uint2*)&C32[(size_t)(rb + g + 8) * DIM + cb] = o1;
            } else {
                float* Cf = (float*)Cp;
                float2 o0 = { v00, v01 };
                float2 o1 = { v10, v11 };
                *(float2*)&Cf[(size_t)(rb + g)     * DIM + cb] = o0;
                *(float2*)&Cf[(size_t)(rb + g + 8) * DIM + cb] = o1;
            }
        }
    }
}

__global__ void __launch_bounds__(256) qkv_kernel()
{
    if (blockIdx.z == 0)      gemm_tile_async<true>(g_x, g_wq, g_q, QBETA, nullptr);
    else if (blockIdx.z == 1) gemm_tile_async<true>(g_x, g_wk, g_k, 1.f, nullptr);
    else                      gemm_tile_async<true>(g_x, g_wv, g_v, 1.f, nullptr);
}

__global__ void __launch_bounds__(256) out_kernel(
    const float* __restrict__ bo, float* __restrict__ out)
{
    gemm_tile_async<false>(g_att, g_wo, out, 1.f, bo);
}

// ---------------------------------------------------------------------------
// Flash attention (unchanged from R8): Br=128 (256 threads, 8 warps),
// Bc=64, K/V double-buffered via cp.async.
// smem: 2 stages x (K[64][68] + V[64][72]) + P[128][68] = 104KB -> 2 blocks/SM.
// ---------------------------------------------------------------------------
#define FL_KLD 68
#define FL_VLD 72
#define FL_PLD 68
#define FL_STAGE_UINTS (64 * FL_KLD + 64 * FL_VLD)        // 8960
#define OFF_KV(b) ((b) * FL_STAGE_UINTS)
#define OFF_P (2 * FL_STAGE_UINTS)
#define FL_SMEM_UINTS (OFF_P + 128 * FL_PLD)
#define FL_SMEM_BYTES (FL_SMEM_UINTS * 4)                 // 106496 B

__device__ __forceinline__ void stage_kv(unsigned* buf, int jt, int hoff, int tid)
{
    unsigned* Ks = buf;
    unsigned* Vs = buf + 64 * FL_KLD;
#pragma unroll
    for (int p = 0; p < 4; p++) {
        const int idx = tid + p * 256;
        const int r  = idx >> 4;
        const int c4 = (idx & 15) * 4;
        cp16(smem_u32(&Ks[r * FL_KLD + c4]),
             &g_k[(size_t)(jt * 64 + r) * DIM + hoff + c4]);
        cp16(smem_u32(&Vs[r * FL_VLD + c4]),
             &g_v[(size_t)(jt * 64 + r) * DIM + hoff + c4]);
    }
    asm volatile("cp.async.commit_group;");
}

__global__ void __launch_bounds__(256, 2) flash_kernel()
{
    extern __shared__ unsigned sm[];
    unsigned* Ps = sm + OFF_P;

    const int tid  = threadIdx.x;
    const int lane = tid & 31;
    const int warp = tid >> 5;
    const int g = lane >> 2;
    const int t = lane & 3;
    const int h   = blockIdx.y;
    const int qt2 = gridDim.x - 1 - blockIdx.x;   // heaviest q-tiles first
    const int hoff = h * DHEAD;
    const int rb = warp * 16;
    const int jtmax = 2 * qt2 + 1;

    stage_kv(sm + OFF_KV(0), 0, hoff, tid);

    // stage Q bits into P region, then hoist fragments (overlaps cp.async)
    {
        const int r = tid >> 1, cb = (tid & 1) * 32;
        const uint4* src = (const uint4*)&g_q[(size_t)(qt2 * 128 + r) * DIM + hoff + cb];
#pragma unroll
        for (int i = 0; i < 8; i++)
            *(uint4*)&Ps[r * FL_PLD + cb + i * 4] = src[i];
    }
    __syncwarp();
    unsigned qa[8][4];
#pragma unroll
    for (int kk = 0; kk < 8; kk++) {
        qa[kk][0] = Ps[(rb + g)     * FL_PLD + kk * 8 + t];
        qa[kk][1] = Ps[(rb + g + 8) * FL_PLD + kk * 8 + t];
        qa[kk][2] = Ps[(rb + g)     * FL_PLD + kk * 8 + t + 4];
        qa[kk][3] = Ps[(rb + g + 8) * FL_PLD + kk * 8 + t + 4];
    }
    __syncwarp();

    float o[8][4];
#pragma unroll
    for (int ni = 0; ni < 8; ni++)
#pragma unroll
        for (int e = 0; e < 4; e++) o[ni][e] = 0.f;
    float m0 = -1e30f, m1 = -1e30f, l0 = 0.f, l1 = 0.f;

    for (int jt = 0; jt <= jtmax; jt++) {
        const int cur = jt & 1;
        unsigned* Ks = sm + OFF_KV(cur);
        unsigned* Vs = Ks + 64 * FL_KLD;

        if (jt < jtmax) {
            stage_kv(sm + OFF_KV(cur ^ 1), jt + 1, hoff, tid);
            asm volatile("cp.async.wait_group 1;");
        } else {
            asm volatile("cp.async.wait_group 0;");
        }
        __syncthreads();

        const bool active = (jt * 64 <= qt2 * 128 + rb + 15);
        if (active) {
            float s[8][4];
#pragma unroll
            for (int ni = 0; ni < 8; ni++)
#pragma unroll
                for (int e = 0; e < 4; e++) s[ni][e] = 0.f;

#pragma unroll
            for (int kk = 0; kk < 8; kk++) {
#pragma unroll
                for (int ni = 0; ni < 8; ni++) {
                    const unsigned b0 = Ks[(ni * 8 + g) * FL_KLD + kk * 8 + t];
                    const unsigned b1 = Ks[(ni * 8 + g) * FL_KLD + kk * 8 + t + 4];
                    mma_tf32(s[ni], qa[kk][0], qa[kk][1], qa[kk][2], qa[kk][3], b0, b1);
                }
            }

            if (jt >= 2 * qt2) {
                const int gr0 = qt2 * 128 + rb + g;
                const int gr1 = gr0 + 8;
                const int cb0 = jt * 64;
#pragma unroll
                for (int ni = 0; ni < 8; ni++) {
                    const int j0 = cb0 + ni * 8 + 2 * t, j1 = j0 + 1;
                    if (j0 > gr0) s[ni][0] = -1e30f;
                    if (j1 > gr0) s[ni][1] = -1e30f;
                    if (j0 > gr1) s[ni][2] = -1e30f;
                    if (j1 > gr1) s[ni][3] = -1e30f;
                }
            }

            float rm0 = -1e30f, rm1 = -1e30f;
#pragma unroll
            for (int ni = 0; ni < 8; ni++) {
                rm0 = fmaxf(rm0, fmaxf(s[ni][0], s[ni][1]));
                rm1 = fmaxf(rm1, fmaxf(s[ni][2], s[ni][3]));
            }
            rm0 = fmaxf(rm0, __shfl_xor_sync(0xffffffffu, rm0, 1));
            rm0 = fmaxf(rm0, __shfl_xor_sync(0xffffffffu, rm0, 2));
            rm1 = fmaxf(rm1, __shfl_xor_sync(0xffffffffu, rm1, 1));
            rm1 = fmaxf(rm1, __shfl_xor_sync(0xffffffffu, rm1, 2));

            const float mn0 = fmaxf(m0, rm0), mn1 = fmaxf(m1, rm1);
            const float corr0 = __expf(m0 - mn0), corr1 = __expf(m1 - mn1);
            m0 = mn0; m1 = mn1;

            float rs0 = 0.f, rs1 = 0.f;
#pragma unroll
            for (int ni = 0; ni < 8; ni++) {
                s[ni][0] = __expf(s[ni][0] - mn0);
                s[ni][1] = __expf(s[ni][1] - mn0);
                s[ni][2] = __expf(s[ni][2] - mn1);
                s[ni][3] = __expf(s[ni][3] - mn1);
                rs0 += s[ni][0] + s[ni][1];
                rs1 += s[ni][2] + s[ni][3];
                Ps[(rb + g)     * FL_PLD + ni * 8 + 2 * t]     = f2tf(s[ni][0]);
                Ps[(rb + g)     * FL_PLD + ni * 8 + 2 * t + 1] = f2tf(s[ni][1]);
                Ps[(rb + g + 8) * FL_PLD + ni * 8 + 2 * t]     = f2tf(s[ni][2]);
                Ps[(rb + g + 8) * FL_PLD + ni * 8 + 2 * t + 1] = f2tf(s[ni][3]);
            }
            rs0 += __shfl_xor_sync(0xffffffffu, rs0, 1);
            rs0 += __shfl_xor_sync(0xffffffffu, rs0, 2);
            rs1 += __shfl_xor_sync(0xffffffffu, rs1, 1);
            rs1 += __shfl_xor_sync(0xffffffffu, rs1, 2);
            l0 = l0 * corr0 + rs0;
            l1 = l1 * corr1 + rs1;

#pragma unroll
            for (int ni = 0; ni < 8; ni++) {
                o[ni][0] *= corr0; o[ni][1] *= corr0;
                o[ni][2] *= corr1; o[ni][3] *= corr1;
            }
            __syncwarp();

#pragma unroll
            for (int kk = 0; kk < 8; kk++) {
                const unsigned a0 = Ps[(rb + g)     * FL_PLD + kk * 8 + t];
                const unsigned a1 = Ps[(rb + g + 8) * FL_PLD + kk * 8 + t];
                const unsigned a2 = Ps[(rb + g)     * FL_PLD + kk * 8 + t + 4];
                const unsigned a3 = Ps[(rb + g + 8) * FL_PLD + kk * 8 + t + 4];
#pragma unroll
                for (int ni = 0; ni < 8; ni++) {
                    const unsigned b0 = Vs[(kk * 8 + t)     * FL_VLD + ni * 8 + g];
                    const unsigned b1 = Vs[(kk * 8 + t + 4) * FL_VLD + ni * 8 + g];
                    mma_tf32(o[ni], a0, a1, a2, a3, b0, b1);
                }
            }
        }
        __syncthreads();
    }

    const float inv0 = 1.f / l0, inv1 = 1.f / l1;
    const int row = qt2 * 128 + rb;
#pragma unroll
    for (int ni = 0; ni < 8; ni++) {
        const int cb = hoff + ni * 8 + 2 * t;
        uint2 v0 = { f2tf(o[ni][0] * inv0), f2tf(o[ni][1] * inv0) };
        uint2 v1 = { f2tf(o[ni][2] * inv1), f2tf(o[ni][3] * inv1) };
        *(uint2*)&g_att[(size_t)(row + g)     * DIM + cb] = v0;
        *(uint2*)&g_att[(size_t)(row + g + 8) * DIM + cb] = v1;
    }
}

// ---------------------------------------------------------------------------
extern "C" void kernel_launch(void* const* d_in, const int* in_sizes, int n_in,
                              void* d_out, int out_size)
{
    const float* x  = (const float*)d_in[0];
    const float* Wq = (const float*)d_in[1];
    const float* Wk = (const float*)d_in[2];
    const float* Wv = (const float*)d_in[3];
    const float* Wo = (const float*)d_in[4];
    const float* bo = (const float*)d_in[5];
    float* out = (float*)d_out;

    cudaFuncSetAttribute(flash_kernel,
                         cudaFuncAttributeMaxDynamicSharedMemorySize, FL_SMEM_BYTES);
    cudaFuncSetAttribute(qkv_kernel,
                         cudaFuncAttributeMaxDynamicSharedMemorySize, G_SMEM_BYTES);
    cudaFuncSetAttribute(out_kernel,
                         cudaFuncAttributeMaxDynamicSharedMemorySize, G_SMEM_BYTES);

    unsigned* gx;  cudaGetSymbolAddress((void**)&gx,  g_x);
    unsigned* gwq; cudaGetSymbolAddress((void**)&gwq, g_wq);
    unsigned* gwk; cudaGetSymbolAddress((void**)&gwk, g_wk);
    unsigned* gwv; cudaGetSymbolAddress((void**)&gwv, g_wv);
    unsigned* gwo; cudaGetSymbolAddress((void**)&gwo, g_wo);

    cvt_kernel<<<SEQ * DIM / 1024, 256>>>(x,  gx);
    cvt_kernel<<<DIM * DIM / 1024, 256>>>(Wq, gwq);
    cvt_kernel<<<DIM * DIM / 1024, 256>>>(Wk, gwk);
    cvt_kernel<<<DIM * DIM / 1024, 256>>>(Wv, gwv);
    cvt_kernel<<<DIM * DIM / 1024, 256>>>(Wo, gwo);

    qkv_kernel<<<dim3(DIM / 64, SEQ / 128, 3), 256, G_SMEM_BYTES>>>();
    flash_kernel<<<dim3(SEQ / 128, HEADS), 256, FL_SMEM_BYTES>>>();
    out_kernel<<<dim3(DIM / 64, SEQ / 128), 256, G_SMEM_BYTES>>>(bo, out);
}

// round 11
// speedup vs baseline: 1.4053x; 1.4053x over previous
#include <cuda_runtime.h>
#include <cstdint>

#define SEQ    4096
#define DIM    1024
#define HEADS  16
#define DHEAD  64
#define QBETA  0.125f   // 1/sqrt(64)

// Scratch (allocation-free rule: __device__ globals).
// All tensors hold tf32 BIT PATTERNS — cvt.rna hoisted to prep kernels;
// values entering every mma are bit-identical to prior rounds.
__device__ unsigned g_q[SEQ * DIM];
__device__ unsigned g_k[SEQ * DIM];
__device__ unsigned g_v[SEQ * DIM];
__device__ unsigned g_att[SEQ * DIM];
__device__ unsigned g_x[SEQ * DIM];
__device__ unsigned g_wq[DIM * DIM];
__device__ unsigned g_wk[DIM * DIM];
__device__ unsigned g_wv[DIM * DIM];
__device__ unsigned g_wo[DIM * DIM];

// ---------------------------------------------------------------------------
// tf32 helpers
// ---------------------------------------------------------------------------
__device__ __forceinline__ unsigned f2tf(float x) {
    unsigned u;
    asm("cvt.rna.tf32.f32 %0, %1;" : "=r"(u) : "f"(x));
    return u;
}

__device__ __forceinline__ void mma_tf32(float* c,
                                         unsigned a0, unsigned a1, unsigned a2, unsigned a3,
                                         unsigned b0, unsigned b1) {
    asm volatile(
        "mma.sync.aligned.m16n8k8.row.col.f32.tf32.tf32.f32 "
        "{%0,%1,%2,%3},{%4,%5,%6,%7},{%8,%9},{%0,%1,%2,%3};"
        : "+f"(c[0]), "+f"(c[1]), "+f"(c[2]), "+f"(c[3])
        : "r"(a0), "r"(a1), "r"(a2), "r"(a3), "r"(b0), "r"(b1));
}

__device__ __forceinline__ unsigned smem_u32(const void* p) {
    return (unsigned)__cvta_generic_to_shared(p);
}
__device__ __forceinline__ void cp16(unsigned dst, const void* src) {
    asm volatile("cp.async.cg.shared.global [%0], [%1], 16;" :: "r"(dst), "l"(src));
}

// ---------------------------------------------------------------------------
// prep: fp32 -> tf32 bits
// ---------------------------------------------------------------------------
__global__ void __launch_bounds__(256) cvt_kernel(
    const float* __restrict__ src, unsigned* __restrict__ dst)
{
    const int i = (blockIdx.x * 256 + threadIdx.x) * 4;
    float4 v = *(const float4*)&src[i];
    uint4 o = { f2tf(v.x), f2tf(v.y), f2tf(v.z), f2tf(v.w) };
    *(uint4*)&dst[i] = o;
}

// ---------------------------------------------------------------------------
// tf32 GEMM: block tile 128x64, K-step 32, register-prefetch double buffer
// (LDG path — preserves cross-block L1 reuse; cp.async deliberately NOT used
// here after the R10 regression). 256 threads = 8 warps (4x2), warp 32x32.
// A ld=36, B ld=72 — conflict-free fragment gathers. ONE barrier per K-step.
// ---------------------------------------------------------------------------
#define GA_LD 36
#define GB_LD 72
#define G_STAGE (128 * GA_LD + 32 * GB_LD)     // 6912 uints
#define G_SMEM_BYTES (2 * G_STAGE * 4)         // 55296 B

template<bool OUT_TF32>
__device__ __forceinline__ void gemm_tile_pipe(
    const unsigned* __restrict__ A, const unsigned* __restrict__ B,
    void* __restrict__ Cp, float alpha, const float* __restrict__ bias)
{
    extern __shared__ unsigned gsm[];

    const int tid  = threadIdx.x;
    const int lane = tid & 31;
    const int warp = tid >> 5;
    const int g = lane >> 2;
    const int t = lane & 3;
    const int wm = warp & 3;
    const int wn = warp >> 2;
    const int row0 = blockIdx.y * 128;
    const int col0 = blockIdx.x * 64;

    // per-thread staging coordinates
    const int ar = tid >> 3;           // A row within 32-row group
    const int ac = (tid & 7) * 4;      // A col (k) offset
    const int br = tid >> 4;           // B row within 16-row group
    const int bc = (tid & 15) * 4;     // B col offset

    uint4 ra[4], rb[2];

    // prologue: load + store stage 0
#pragma unroll
    for (int p = 0; p < 4; p++)
        ra[p] = *(const uint4*)&A[(size_t)(row0 + ar + p * 32) * DIM + ac];
#pragma unroll
    for (int p = 0; p < 2; p++)
        rb[p] = *(const uint4*)&B[(size_t)(br + p * 16) * DIM + col0 + bc];
    {
        unsigned* As = gsm;
        unsigned* Bs = gsm + 128 * GA_LD;
#pragma unroll
        for (int p = 0; p < 4; p++) *(uint4*)&As[(ar + p * 32) * GA_LD + ac] = ra[p];
#pragma unroll
        for (int p = 0; p < 2; p++) *(uint4*)&Bs[(br + p * 16) * GB_LD + bc] = rb[p];
    }
    __syncthreads();

    float acc[2][4][4];
#pragma unroll
    for (int mi = 0; mi < 2; mi++)
#pragma unroll
        for (int ni = 0; ni < 4; ni++)
#pragma unroll
            for (int e = 0; e < 4; e++) acc[mi][ni][e] = 0.f;

#pragma unroll 2
    for (int ks = 0; ks < DIM / 32; ks++) {
        unsigned* As = gsm + (ks & 1) * G_STAGE;
        unsigned* Bs = As + 128 * GA_LD;

        // prefetch next K-step into registers (latency hidden by compute)
        if (ks < DIM / 32 - 1) {
            const int k0 = (ks + 1) * 32;
#pragma unroll
            for (int p = 0; p < 4; p++)
                ra[p] = *(const uint4*)&A[(size_t)(row0 + ar + p * 32) * DIM + k0 + ac];
#pragma unroll
            for (int p = 0; p < 2; p++)
                rb[p] = *(const uint4*)&B[(size_t)(k0 + br + p * 16) * DIM + col0 + bc];
        }

        // compute on current stage
#pragma unroll
        for (int kk = 0; kk < 4; kk++) {
            unsigned a[2][4];
#pragma unroll
            for (int mi = 0; mi < 2; mi++) {
                const int rbm = wm * 32 + mi * 16;
                a[mi][0] = As[(rbm + g)     * GA_LD + kk * 8 + t];
                a[mi][1] = As[(rbm + g + 8) * GA_LD + kk * 8 + t];
                a[mi][2] = As[(rbm + g)     * GA_LD + kk * 8 + t + 4];
                a[mi][3] = As[(rbm + g + 8) * GA_LD + kk * 8 + t + 4];
            }
#pragma unroll
            for (int ni = 0; ni < 4; ni++) {
                const unsigned b0 = Bs[(kk * 8 + t)     * GB_LD + wn * 32 + ni * 8 + g];
                const unsigned b1 = Bs[(kk * 8 + t + 4) * GB_LD + wn * 32 + ni * 8 + g];
                mma_tf32(acc[0][ni], a[0][0], a[0][1], a[0][2], a[0][3], b0, b1);
                mma_tf32(acc[1][ni], a[1][0], a[1][1], a[1][2], a[1][3], b0, b1);
            }
        }

        // store prefetched data into the other stage
        if (ks < DIM / 32 - 1) {
            unsigned* Ad = gsm + ((ks & 1) ^ 1) * G_STAGE;
            unsigned* Bd = Ad + 128 * GA_LD;
#pragma unroll
            for (int p = 0; p < 4; p++) *(uint4*)&Ad[(ar + p * 32) * GA_LD + ac] = ra[p];
#pragma unroll
            for (int p = 0; p < 2; p++) *(uint4*)&Bd[(br + p * 16) * GB_LD + bc] = rb[p];
        }
        __syncthreads();
    }

    // epilogue
#pragma unroll
    for (int mi = 0; mi < 2; mi++) {
        const int rbw = row0 + wm * 32 + mi * 16;
#pragma unroll
        for (int ni = 0; ni < 4; ni++) {
            const int cb = col0 + wn * 32 + ni * 8 + 2 * t;
            float bv0 = 0.f, bv1 = 0.f;
            if (bias) { bv0 = bias[cb]; bv1 = bias[cb + 1]; }
            float v00 = acc[mi][ni][0] * alpha + bv0;
            float v01 = acc[mi][ni][1] * alpha + bv1;
            float v10 = acc[mi][ni][2] * alpha + bv0;
            float v11 = acc[mi][ni][3] * alpha + bv1;
            if (OUT_TF32) {
                unsigned* C32 = (unsigned*)Cp;
                uint2 o0 = { f2tf(v00), f2tf(v01) };
                uint2 o1 = { f2tf(v10), f2tf(v11) };
                *(uint2*)&C32[(size_t)(rbw + g)     * DIM + cb] = o0;
                *(uint2*)&C32[(size_t)(rbw + g + 8) * DIM + cb] = o1;
            } else {
                float* Cf = (float*)Cp;
                float2 o0 = { v00, v01 };
                float2 o1 = { v10, v11 };
                *(float2*)&Cf[(size_t)(rbw + g)     * DIM + cb] = o0;
                *(float2*)&Cf[(size_t)(rbw + g + 8) * DIM + cb] = o1;
            }
        }
    }
}

__global__ void __launch_bounds__(256, 3) qkv_kernel()
{
    if (blockIdx.z == 0)      gemm_tile_pipe<true>(g_x, g_wq, g_q, QBETA, nullptr);
    else if (blockIdx.z == 1) gemm_tile_pipe<true>(g_x, g_wk, g_k, 1.f, nullptr);
    else                      gemm_tile_pipe<true>(g_x, g_wv, g_v, 1.f, nullptr);
}

__global__ void __launch_bounds__(256, 3) out_kernel(
    const float* __restrict__ bo, float* __restrict__ out)
{
    gemm_tile_pipe<false>(g_att, g_wo, out, 1.f, bo);
}

// ---------------------------------------------------------------------------
// Flash attention (R8, proven): Br=128 (256 threads, 8 warps), Bc=64,
// K/V double-buffered via cp.async (no same-SM reuse -> cp.async is right here).
// smem: 2 x (K[64][68] + V[64][72]) + P[128][68] = 104KB -> 2 blocks/SM.
// ---------------------------------------------------------------------------
#define FL_KLD 68
#define FL_VLD 72
#define FL_PLD 68
#define FL_STAGE_UINTS (64 * FL_KLD + 64 * FL_VLD)
#define OFF_KV(b) ((b) * FL_STAGE_UINTS)
#define OFF_P (2 * FL_STAGE_UINTS)
#define FL_SMEM_UINTS (OFF_P + 128 * FL_PLD)
#define FL_SMEM_BYTES (FL_SMEM_UINTS * 4)

__device__ __forceinline__ void stage_kv(unsigned* buf, int jt, int hoff, int tid)
{
    unsigned* Ks = buf;
    unsigned* Vs = buf + 64 * FL_KLD;
#pragma unroll
    for (int p = 0; p < 4; p++) {
        const int idx = tid + p * 256;
        const int r  = idx >> 4;
        const int c4 = (idx & 15) * 4;
        cp16(smem_u32(&Ks[r * FL_KLD + c4]),
             &g_k[(size_t)(jt * 64 + r) * DIM + hoff + c4]);
        cp16(smem_u32(&Vs[r * FL_VLD + c4]),
             &g_v[(size_t)(jt * 64 + r) * DIM + hoff + c4]);
    }
    asm volatile("cp.async.commit_group;");
}

__global__ void __launch_bounds__(256, 2) flash_kernel()
{
    extern __shared__ unsigned sm[];
    unsigned* Ps = sm + OFF_P;

    const int tid  = threadIdx.x;
    const int lane = tid & 31;
    const int warp = tid >> 5;
    const int g = lane >> 2;
    const int t = lane & 3;
    const int h   = blockIdx.y;
    const int qt2 = gridDim.x - 1 - blockIdx.x;
    const int hoff = h * DHEAD;
    const int rb = warp * 16;
    const int jtmax = 2 * qt2 + 1;

    stage_kv(sm + OFF_KV(0), 0, hoff, tid);

    {
        const int r = tid >> 1, cb = (tid & 1) * 32;
        const uint4* src = (const uint4*)&g_q[(size_t)(qt2 * 128 + r) * DIM + hoff + cb];
#pragma unroll
        for (int i = 0; i < 8; i++)
            *(uint4*)&Ps[r * FL_PLD + cb + i * 4] = src[i];
    }
    __syncwarp();
    unsigned qa[8][4];
#pragma unroll
    for (int kk = 0; kk < 8; kk++) {
        qa[kk][0] = Ps[(rb + g)     * FL_PLD + kk * 8 + t];
        qa[kk][1] = Ps[(rb + g + 8) * FL_PLD + kk * 8 + t];
        qa[kk][2] = Ps[(rb + g)     * FL_PLD + kk * 8 + t + 4];
        qa[kk][3] = Ps[(rb + g + 8) * FL_PLD + kk * 8 + t + 4];
    }
    __syncwarp();

    float o[8][4];
#pragma unroll
    for (int ni = 0; ni < 8; ni++)
#pragma unroll
        for (int e = 0; e < 4; e++) o[ni][e] = 0.f;
    float m0 = -1e30f, m1 = -1e30f, l0 = 0.f, l1 = 0.f;

    for (int jt = 0; jt <= jtmax; jt++) {
        const int cur = jt & 1;
        unsigned* Ks = sm + OFF_KV(cur);
        unsigned* Vs = Ks + 64 * FL_KLD;

        if (jt < jtmax) {
            stage_kv(sm + OFF_KV(cur ^ 1), jt + 1, hoff, tid);
            asm volatile("cp.async.wait_group 1;");
        } else {
            asm volatile("cp.async.wait_group 0;");
        }
        __syncthreads();

        const bool active = (jt * 64 <= qt2 * 128 + rb + 15);
        if (active) {
            float s[8][4];
#pragma unroll
            for (int ni = 0; ni < 8; ni++)
#pragma unroll
                for (int e = 0; e < 4; e++) s[ni][e] = 0.f;

#pragma unroll
            for (int kk = 0; kk < 8; kk++) {
#pragma unroll
                for (int ni = 0; ni < 8; ni++) {
                    const unsigned b0 = Ks[(ni * 8 + g) * FL_KLD + kk * 8 + t];
                    const unsigned b1 = Ks[(ni * 8 + g) * FL_KLD + kk * 8 + t + 4];
                    mma_tf32(s[ni], qa[kk][0], qa[kk][1], qa[kk][2], qa[kk][3], b0, b1);
                }
            }

            if (jt >= 2 * qt2) {
                const int gr0 = qt2 * 128 + rb + g;
                const int gr1 = gr0 + 8;
                const int cb0 = jt * 64;
#pragma unroll
                for (int ni = 0; ni < 8; ni++) {
                    const int j0 = cb0 + ni * 8 + 2 * t, j1 = j0 + 1;
                    if (j0 > gr0) s[ni][0] = -1e30f;
                    if (j1 > gr0) s[ni][1] = -1e30f;
                    if (j0 > gr1) s[ni][2] = -1e30f;
                    if (j1 > gr1) s[ni][3] = -1e30f;
                }
            }

            float rm0 = -1e30f, rm1 = -1e30f;
#pragma unroll
            for (int ni = 0; ni < 8; ni++) {
                rm0 = fmaxf(rm0, fmaxf(s[ni][0], s[ni][1]));
                rm1 = fmaxf(rm1, fmaxf(s[ni][2], s[ni][3]));
            }
            rm0 = fmaxf(rm0, __shfl_xor_sync(0xffffffffu, rm0, 1));
            rm0 = fmaxf(rm0, __shfl_xor_sync(0xffffffffu, rm0, 2));
            rm1 = fmaxf(rm1, __shfl_xor_sync(0xffffffffu, rm1, 1));
            rm1 = fmaxf(rm1, __shfl_xor_sync(0xffffffffu, rm1, 2));

            const float mn0 = fmaxf(m0, rm0), mn1 = fmaxf(m1, rm1);
            const float corr0 = __expf(m0 - mn0), corr1 = __expf(m1 - mn1);
            m0 = mn0; m1 = mn1;

            float rs0 = 0.f, rs1 = 0.f;
#pragma unroll
            for (int ni = 0; ni < 8; ni++) {
                s[ni][0] = __expf(s[ni][0] - mn0);
                s[ni][1] = __expf(s[ni][1] - mn0);
                s[ni][2] = __expf(s[ni][2] - mn1);
                s[ni][3] = __expf(s[ni][3] - mn1);
                rs0 += s[ni][0] + s[ni][1];
                rs1 += s[ni][2] + s[ni][3];
                Ps[(rb + g)     * FL_PLD + ni * 8 + 2 * t]     = f2tf(s[ni][0]);
                Ps[(rb + g)     * FL_PLD + ni * 8 + 2 * t + 1] = f2tf(s[ni][1]);
                Ps[(rb + g + 8) * FL_PLD + ni * 8 + 2 * t]     = f2tf(s[ni][2]);
                Ps[(rb + g + 8) * FL_PLD + ni * 8 + 2 * t + 1] = f2tf(s[ni][3]);
            }
            rs0 += __shfl_xor_sync(0xffffffffu, rs0, 1);
            rs0 += __shfl_xor_sync(0xffffffffu, rs0, 2);
            rs1 += __shfl_xor_sync(0xffffffffu, rs1, 1);
            rs1 += __shfl_xor_sync(0xffffffffu, rs1, 2);
            l0 = l0 * corr0 + rs0;
            l1 = l1 * corr1 + rs1;

#pragma unroll
            for (int ni = 0; ni < 8; ni++) {
                o[ni][0] *= corr0; o[ni][1] *= corr0;
                o[ni][2] *= corr1; o[ni][3] *= corr1;
            }
            __syncwarp();

#pragma unroll
            for (int kk = 0; kk < 8; kk++) {
                const unsigned a0 = Ps[(rb + g)     * FL_PLD + kk * 8 + t];
                const unsigned a1 = Ps[(rb + g + 8) * FL_PLD + kk * 8 + t];
                const unsigned a2 = Ps[(rb + g)     * FL_PLD + kk * 8 + t + 4];
                const unsigned a3 = Ps[(rb + g + 8) * FL_PLD + kk * 8 + t + 4];
#pragma unroll
                for (int ni = 0; ni < 8; ni++) {
                    const unsigned b0 = Vs[(kk * 8 + t)     * FL_VLD + ni * 8 + g];
                    const unsigned b1 = Vs[(kk * 8 + t + 4) * FL_VLD + ni * 8 + g];
                    mma_tf32(o[ni], a0, a1, a2, a3, b0, b1);
                }
            }
        }
        __syncthreads();
    }

    const float inv0 = 1.f / l0, inv1 = 1.f / l1;
    const int row = qt2 * 128 + rb;
#pragma unroll
    for (int ni = 0; ni < 8; ni++) {
        const int cb = hoff + ni * 8 + 2 * t;
        uint2 v0 = { f2tf(o[ni][0] * inv0), f2tf(o[ni][1] * inv0) };
        uint2 v1 = { f2tf(o[ni][2] * inv1), f2tf(o[ni][3] * inv1) };
        *(uint2*)&g_att[(size_t)(row + g)     * DIM + cb] = v0;
        *(uint2*)&g_att[(size_t)(row + g + 8) * DIM + cb] = v1;
    }
}

// ---------------------------------------------------------------------------
extern "C" void kernel_launch(void* const* d_in, const int* in_sizes, int n_in,
                              void* d_out, int out_size)
{
    const float* x  = (const float*)d_in[0];
    const float* Wq = (const float*)d_in[1];
    const float* Wk = (const float*)d_in[2];
    const float* Wv = (const float*)d_in[3];
    const float* Wo = (const float*)d_in[4];
    const float* bo = (const float*)d_in[5];
    float* out = (float*)d_out;

    cudaFuncSetAttribute(flash_kernel,
                         cudaFuncAttributeMaxDynamicSharedMemorySize, FL_SMEM_BYTES);
    cudaFuncSetAttribute(qkv_kernel,
                         cudaFuncAttributeMaxDynamicSharedMemorySize, G_SMEM_BYTES);
    cudaFuncSetAttribute(out_kernel,
                         cudaFuncAttributeMaxDynamicSharedMemorySize, G_SMEM_BYTES);

    unsigned* gx;  cudaGetSymbolAddress((void**)&gx,  g_x);
    unsigned* gwq; cudaGetSymbolAddress((void**)&gwq, g_wq);
    unsigned* gwk; cudaGetSymbolAddress((void**)&gwk, g_wk);
    unsigned* gwv; cudaGetSymbolAddress((void**)&gwv, g_wv);
    unsigned* gwo; cudaGetSymbolAddress((void**)&gwo, g_wo);

    cvt_kernel<<<SEQ * DIM / 1024, 256>>>(x,  gx);
    cvt_kernel<<<DIM * DIM / 1024, 256>>>(Wq, gwq);
    cvt_kernel<<<DIM * DIM / 1024, 256>>>(Wk, gwk);
    cvt_kernel<<<DIM * DIM / 1024, 256>>>(Wv, gwv);
    cvt_kernel<<<DIM * DIM / 1024, 256>>>(Wo, gwo);

    qkv_kernel<<<dim3(DIM / 64, SEQ / 128, 3), 256, G_SMEM_BYTES>>>();
    flash_kernel<<<dim3(SEQ / 128, HEADS), 256, FL_SMEM_BYTES>>>();
    out_kernel<<<dim3(DIM / 64, SEQ / 128), 256, G_SMEM_BYTES>>>(bo, out);
}

// round 12
// speedup vs baseline: 1.6869x; 1.2004x over previous
#include <cuda_runtime.h>
#include <cstdint>

#define SEQ    4096
#define DIM    1024
#define HEADS  16
#define DHEAD  64
#define QBETA  0.125f   // 1/sqrt(64)
#define NUNITS (HEADS * (SEQ / 128))   // 512 work units

// Scratch (allocation-free rule: __device__ globals).
// Q/K/V/att hold tf32 BIT PATTERNS — rounding just happens earlier; numerics identical.
__device__ unsigned g_q[SEQ * DIM];
__device__ unsigned g_k[SEQ * DIM];
__device__ unsigned g_v[SEQ * DIM];
__device__ unsigned g_att[SEQ * DIM];
__device__ int g_ctr;

// ---------------------------------------------------------------------------
// tf32 helpers
// ---------------------------------------------------------------------------
__device__ __forceinline__ unsigned f2tf(float x) {
    unsigned u;
    asm("cvt.rna.tf32.f32 %0, %1;" : "=r"(u) : "f"(x));
    return u;
}

__device__ __forceinline__ void mma_tf32(float* c,
                                         unsigned a0, unsigned a1, unsigned a2, unsigned a3,
                                         unsigned b0, unsigned b1) {
    asm volatile(
        "mma.sync.aligned.m16n8k8.row.col.f32.tf32.tf32.f32 "
        "{%0,%1,%2,%3},{%4,%5,%6,%7},{%8,%9},{%0,%1,%2,%3};"
        : "+f"(c[0]), "+f"(c[1]), "+f"(c[2]), "+f"(c[3])
        : "r"(a0), "r"(a1), "r"(a2), "r"(a3), "r"(b0), "r"(b1));
}

__device__ __forceinline__ unsigned smem_u32(const void* p) {
    return (unsigned)__cvta_generic_to_shared(p);
}
__device__ __forceinline__ void cp16(unsigned dst, const void* src) {
    asm volatile("cp.async.cg.shared.global [%0], [%1], 16;" :: "r"(dst), "l"(src));
}

// ---------------------------------------------------------------------------
// tf32 GEMM (R8-proven): block tile 128x64, K-step 32, sync LDG staging
// (L1 reuse across co-resident blocks; cp.async/prefetch variants both lost).
// 256 threads = 8 warps (4x2), warp tile 32x32. A ld=36, B ld=72.
// ---------------------------------------------------------------------------
#define GA_LD 36
#define GB_LD 72

template<bool A_TF32, bool OUT_TF32>
__device__ __forceinline__ void gemm_tile(
    const void* __restrict__ Ap, const float* __restrict__ B,
    void* __restrict__ Cp, float alpha, const float* __restrict__ bias)
{
    __shared__ unsigned As[128 * GA_LD];
    __shared__ unsigned Bs[32 * GB_LD];

    const int tid  = threadIdx.x;
    const int lane = tid & 31;
    const int warp = tid >> 5;
    const int g = lane >> 2;
    const int t = lane & 3;
    const int wm = warp & 3;
    const int wn = warp >> 2;
    const int row0 = blockIdx.y * 128;
    const int col0 = blockIdx.x * 64;

    float acc[2][4][4];
#pragma unroll
    for (int mi = 0; mi < 2; mi++)
#pragma unroll
        for (int ni = 0; ni < 4; ni++)
#pragma unroll
            for (int e = 0; e < 4; e++) acc[mi][ni][e] = 0.f;

    for (int k0 = 0; k0 < DIM; k0 += 32) {
#pragma unroll
        for (int p = 0; p < 4; p++) {
            const int r = (tid >> 3) + p * 32;
            const int c = (tid & 7) * 4;
            if (A_TF32) {
                const unsigned* A32 = (const unsigned*)Ap;
                *(uint4*)&As[r * GA_LD + c] =
                    *(const uint4*)&A32[(size_t)(row0 + r) * DIM + k0 + c];
            } else {
                const float* Af = (const float*)Ap;
                float4 v = *(const float4*)&Af[(size_t)(row0 + r) * DIM + k0 + c];
                unsigned* d = &As[r * GA_LD + c];
                d[0] = f2tf(v.x); d[1] = f2tf(v.y); d[2] = f2tf(v.z); d[3] = f2tf(v.w);
            }
        }
#pragma unroll
        for (int p = 0; p < 2; p++) {
            const int r = (tid >> 4) + p * 16;
            const int c = (tid & 15) * 4;
            float4 v = *(const float4*)&B[(size_t)(k0 + r) * DIM + col0 + c];
            unsigned* d = &Bs[r * GB_LD + c];
            d[0] = f2tf(v.x); d[1] = f2tf(v.y); d[2] = f2tf(v.z); d[3] = f2tf(v.w);
        }
        __syncthreads();

#pragma unroll
        for (int kk = 0; kk < 4; kk++) {
            unsigned a[2][4];
#pragma unroll
            for (int mi = 0; mi < 2; mi++) {
                const int rbm = wm * 32 + mi * 16;
                a[mi][0] = As[(rbm + g)     * GA_LD + kk * 8 + t];
                a[mi][1] = As[(rbm + g + 8) * GA_LD + kk * 8 + t];
                a[mi][2] = As[(rbm + g)     * GA_LD + kk * 8 + t + 4];
                a[mi][3] = As[(rbm + g + 8) * GA_LD + kk * 8 + t + 4];
            }
#pragma unroll
            for (int ni = 0; ni < 4; ni++) {
                const unsigned b0 = Bs[(kk * 8 + t)     * GB_LD + wn * 32 + ni * 8 + g];
                const unsigned b1 = Bs[(kk * 8 + t + 4) * GB_LD + wn * 32 + ni * 8 + g];
                mma_tf32(acc[0][ni], a[0][0], a[0][1], a[0][2], a[0][3], b0, b1);
                mma_tf32(acc[1][ni], a[1][0], a[1][1], a[1][2], a[1][3], b0, b1);
            }
        }
        __syncthreads();
    }

#pragma unroll
    for (int mi = 0; mi < 2; mi++) {
        const int rb = row0 + wm * 32 + mi * 16;
#pragma unroll
        for (int ni = 0; ni < 4; ni++) {
            const int cb = col0 + wn * 32 + ni * 8 + 2 * t;
            float bv0 = 0.f, bv1 = 0.f;
            if (bias) { bv0 = bias[cb]; bv1 = bias[cb + 1]; }
            float v00 = acc[mi][ni][0] * alpha + bv0;
            float v01 = acc[mi][ni][1] * alpha + bv1;
            float v10 = acc[mi][ni][2] * alpha + bv0;
            float v11 = acc[mi][ni][3] * alpha + bv1;
            if (OUT_TF32) {
                unsigned* C32 = (unsigned*)Cp;
                uint2 o0 = { f2tf(v00), f2tf(v01) };
                uint2 o1 = { f2tf(v10), f2tf(v11) };
                *(uint2*)&C32[(size_t)(rb + g)     * DIM + cb] = o0;
                *(uint2*)&C32[(size_t)(rb + g + 8) * DIM + cb] = o1;
            } else {
                float* Cf = (float*)Cp;
                float2 o0 = { v00, v01 };
                float2 o1 = { v10, v11 };
                *(float2*)&Cf[(size_t)(rb + g)     * DIM + cb] = o0;
                *(float2*)&Cf[(size_t)(rb + g + 8) * DIM + cb] = o1;
            }
        }
    }
}

__global__ void __launch_bounds__(256) qkv_kernel(
    const float* __restrict__ x,
    const float* __restrict__ Wq,
    const float* __restrict__ Wk,
    const float* __restrict__ Wv)
{
    if (blockIdx.z == 0)      gemm_tile<false, true>(x, Wq, g_q, QBETA, nullptr);
    else if (blockIdx.z == 1) gemm_tile<false, true>(x, Wk, g_k, 1.f, nullptr);
    else                      gemm_tile<false, true>(x, Wv, g_v, 1.f, nullptr);
}

__global__ void __launch_bounds__(256) out_kernel(
    const float* __restrict__ bo, float* __restrict__ out)
{
    gemm_tile<true, false>(g_att, nullptr, out, 1.f, bo);   // B unused in A_TF32? no — B needed
}

// NOTE: out_kernel needs Wo as float input; fix signature below (kept explicit).
__global__ void __launch_bounds__(256) out_kernel2(
    const float* __restrict__ Wo,
    const float* __restrict__ bo, float* __restrict__ out)
{
    gemm_tile<true, false>(g_att, Wo, out, 1.f, bo);
}

__global__ void reset_ctr_kernel() { g_ctr = 0; }

// ---------------------------------------------------------------------------
// Flash attention (R8 body) wrapped in a work-stealing persistent loop.
// Units = (head, qt2) ordered heaviest-first; LPT-balanced via atomicAdd.
// smem: 2 x (K[64][68] + V[64][72]) + P[128][68] = 104KB -> 2 blocks/SM.
// ---------------------------------------------------------------------------
#define FL_KLD 68
#define FL_VLD 72
#define FL_PLD 68
#define FL_STAGE_UINTS (64 * FL_KLD + 64 * FL_VLD)
#define OFF_KV(b) ((b) * FL_STAGE_UINTS)
#define OFF_P (2 * FL_STAGE_UINTS)
#define FL_SMEM_UINTS (OFF_P + 128 * FL_PLD)
#define FL_SMEM_BYTES (FL_SMEM_UINTS * 4)

__device__ __forceinline__ void stage_kv(unsigned* buf, int jt, int hoff, int tid)
{
    unsigned* Ks = buf;
    unsigned* Vs = buf + 64 * FL_KLD;
#pragma unroll
    for (int p = 0; p < 4; p++) {
        const int idx = tid + p * 256;
        const int r  = idx >> 4;
        const int c4 = (idx & 15) * 4;
        cp16(smem_u32(&Ks[r * FL_KLD + c4]),
             &g_k[(size_t)(jt * 64 + r) * DIM + hoff + c4]);
        cp16(smem_u32(&Vs[r * FL_VLD + c4]),
             &g_v[(size_t)(jt * 64 + r) * DIM + hoff + c4]);
    }
    asm volatile("cp.async.commit_group;");
}

__global__ void __launch_bounds__(256, 2) flash_kernel()
{
    extern __shared__ unsigned sm[];
    unsigned* Ps = sm + OFF_P;
    __shared__ int s_unit;

    const int tid  = threadIdx.x;
    const int lane = tid & 31;
    const int warp = tid >> 5;
    const int g = lane >> 2;
    const int t = lane & 3;
    const int rb = warp * 16;

    for (;;) {
        if (tid == 0) s_unit = atomicAdd(&g_ctr, 1);
        __syncthreads();                 // broadcasts s_unit; also fences prior unit's smem use
        const int unit = s_unit;
        if (unit >= NUNITS) return;

        const int qt2 = (SEQ / 128 - 1) - (unit >> 4);   // heaviest first
        const int h   = unit & 15;
        const int hoff = h * DHEAD;
        const int jtmax = 2 * qt2 + 1;

        stage_kv(sm + OFF_KV(0), 0, hoff, tid);

        // stage Q bits into P region, then hoist fragments (overlaps cp.async)
        {
            const int r = tid >> 1, cb = (tid & 1) * 32;
            const uint4* src = (const uint4*)&g_q[(size_t)(qt2 * 128 + r) * DIM + hoff + cb];
#pragma unroll
            for (int i = 0; i < 8; i++)
                *(uint4*)&Ps[r * FL_PLD + cb + i * 4] = src[i];
        }
        __syncwarp();
        unsigned qa[8][4];
#pragma unroll
        for (int kk = 0; kk < 8; kk++) {
            qa[kk][0] = Ps[(rb + g)     * FL_PLD + kk * 8 + t];
            qa[kk][1] = Ps[(rb + g + 8) * FL_PLD + kk * 8 + t];
            qa[kk][2] = Ps[(rb + g)     * FL_PLD + kk * 8 + t + 4];
            qa[kk][3] = Ps[(rb + g + 8) * FL_PLD + kk * 8 + t + 4];
        }
        __syncwarp();

        float o[8][4];
#pragma unroll
        for (int ni = 0; ni < 8; ni++)
#pragma unroll
            for (int e = 0; e < 4; e++) o[ni][e] = 0.f;
        float m0 = -1e30f, m1 = -1e30f, l0 = 0.f, l1 = 0.f;

        for (int jt = 0; jt <= jtmax; jt++) {
            const int cur = jt & 1;
            unsigned* Ks = sm + OFF_KV(cur);
            unsigned* Vs = Ks + 64 * FL_KLD;

            if (jt < jtmax) {
                stage_kv(sm + OFF_KV(cur ^ 1), jt + 1, hoff, tid);
                asm volatile("cp.async.wait_group 1;");
            } else {
                asm volatile("cp.async.wait_group 0;");
            }
            __syncthreads();

            const bool active = (jt * 64 <= qt2 * 128 + rb + 15);
            if (active) {
                float s[8][4];
#pragma unroll
                for (int ni = 0; ni < 8; ni++)
#pragma unroll
                    for (int e = 0; e < 4; e++) s[ni][e] = 0.f;

#pragma unroll
                for (int kk = 0; kk < 8; kk++) {
#pragma unroll
                    for (int ni = 0; ni < 8; ni++) {
                        const unsigned b0 = Ks[(ni * 8 + g) * FL_KLD + kk * 8 + t];
                        const unsigned b1 = Ks[(ni * 8 + g) * FL_KLD + kk * 8 + t + 4];
                        mma_tf32(s[ni], qa[kk][0], qa[kk][1], qa[kk][2], qa[kk][3], b0, b1);
                    }
                }

                if (jt >= 2 * qt2) {
                    const int gr0 = qt2 * 128 + rb + g;
                    const int gr1 = gr0 + 8;
                    const int cb0 = jt * 64;
#pragma unroll
                    for (int ni = 0; ni < 8; ni++) {
                        const int j0 = cb0 + ni * 8 + 2 * t, j1 = j0 + 1;
                        if (j0 > gr0) s[ni][0] = -1e30f;
                        if (j1 > gr0) s[ni][1] = -1e30f;
                        if (j0 > gr1) s[ni][2] = -1e30f;
                        if (j1 > gr1) s[ni][3] = -1e30f;
                    }
                }

                float rm0 = -1e30f, rm1 = -1e30f;
#pragma unroll
                for (int ni = 0; ni < 8; ni++) {
                    rm0 = fmaxf(rm0, fmaxf(s[ni][0], s[ni][1]));
                    rm1 = fmaxf(rm1, fmaxf(s[ni][2], s[ni][3]));
                }
                rm0 = fmaxf(rm0, __shfl_xor_sync(0xffffffffu, rm0, 1));
                rm0 = fmaxf(rm0, __shfl_xor_sync(0xffffffffu, rm0, 2));
                rm1 = fmaxf(rm1, __shfl_xor_sync(0xffffffffu, rm1, 1));
                rm1 = fmaxf(rm1, __shfl_xor_sync(0xffffffffu, rm1, 2));

                const float mn0 = fmaxf(m0, rm0), mn1 = fmaxf(m1, rm1);
                const float corr0 = __expf(m0 - mn0), corr1 = __expf(m1 - mn1);
                m0 = mn0; m1 = mn1;

                float rs0 = 0.f, rs1 = 0.f;
#pragma unroll
                for (int ni = 0; ni < 8; ni++) {
                    s[ni][0] = __expf(s[ni][0] - mn0);
                    s[ni][1] = __expf(s[ni][1] - mn0);
                    s[ni][2] = __expf(s[ni][2] - mn1);
                    s[ni][3] = __expf(s[ni][3] - mn1);
                    rs0 += s[ni][0] + s[ni][1];
                    rs1 += s[ni][2] + s[ni][3];
                    Ps[(rb + g)     * FL_PLD + ni * 8 + 2 * t]     = f2tf(s[ni][0]);
                    Ps[(rb + g)     * FL_PLD + ni * 8 + 2 * t + 1] = f2tf(s[ni][1]);
                    Ps[(rb + g + 8) * FL_PLD + ni * 8 + 2 * t]     = f2tf(s[ni][2]);
                    Ps[(rb + g + 8) * FL_PLD + ni * 8 + 2 * t + 1] = f2tf(s[ni][3]);
                }
                rs0 += __shfl_xor_sync(0xffffffffu, rs0, 1);
                rs0 += __shfl_xor_sync(0xffffffffu, rs0, 2);
                rs1 += __shfl_xor_sync(0xffffffffu, rs1, 1);
                rs1 += __shfl_xor_sync(0xffffffffu, rs1, 2);
                l0 = l0 * corr0 + rs0;
                l1 = l1 * corr1 + rs1;

#pragma unroll
                for (int ni = 0; ni < 8; ni++) {
                    o[ni][0] *= corr0; o[ni][1] *= corr0;
                    o[ni][2] *= corr1; o[ni][3] *= corr1;
                }
                __syncwarp();

#pragma unroll
                for (int kk = 0; kk < 8; kk++) {
                    const unsigned a0 = Ps[(rb + g)     * FL_PLD + kk * 8 + t];
                    const unsigned a1 = Ps[(rb + g + 8) * FL_PLD + kk * 8 + t];
                    const unsigned a2 = Ps[(rb + g)     * FL_PLD + kk * 8 + t + 4];
                    const unsigned a3 = Ps[(rb + g + 8) * FL_PLD + kk * 8 + t + 4];
#pragma unroll
                    for (int ni = 0; ni < 8; ni++) {
                        const unsigned b0 = Vs[(kk * 8 + t)     * FL_VLD + ni * 8 + g];
                        const unsigned b1 = Vs[(kk * 8 + t + 4) * FL_VLD + ni * 8 + g];
                        mma_tf32(o[ni], a0, a1, a2, a3, b0, b1);
                    }
                }
            }
            __syncthreads();
        }

        const float inv0 = 1.f / l0, inv1 = 1.f / l1;
        const int row = qt2 * 128 + rb;
#pragma unroll
        for (int ni = 0; ni < 8; ni++) {
            const int cb = hoff + ni * 8 + 2 * t;
            uint2 v0 = { f2tf(o[ni][0] * inv0), f2tf(o[ni][1] * inv0) };
            uint2 v1 = { f2tf(o[ni][2] * inv1), f2tf(o[ni][3] * inv1) };
            *(uint2*)&g_att[(size_t)(row + g)     * DIM + cb] = v0;
            *(uint2*)&g_att[(size_t)(row + g + 8) * DIM + cb] = v1;
        }
    }
}

// ---------------------------------------------------------------------------
extern "C" void kernel_launch(void* const* d_in, const int* in_sizes, int n_in,
                              void* d_out, int out_size)
{
    const float* x  = (const float*)d_in[0];
    const float* Wq = (const float*)d_in[1];
    const float* Wk = (const float*)d_in[2];
    const float* Wv = (const float*)d_in[3];
    const float* Wo = (const float*)d_in[4];
    const float* bo = (const float*)d_in[5];
    float* out = (float*)d_out;

    cudaFuncSetAttribute(flash_kernel,
                         cudaFuncAttributeMaxDynamicSharedMemorySize, FL_SMEM_BYTES);

    qkv_kernel<<<dim3(DIM / 64, SEQ / 128, 3), 256>>>(x, Wq, Wk, Wv);
    reset_ctr_kernel<<<1, 1>>>();
    flash_kernel<<<dim3(SEQ / 128, HEADS), 256, FL_SMEM_BYTES>>>();
    out_kernel2<<<dim3(DIM / 64, SEQ / 128), 256>>>(Wo, bo, out);
}